// round 1
// baseline (speedup 1.0000x reference)
#include <cuda_runtime.h>

// Problem constants
#define BB   4
#define NN   256
#define OBSD 40
#define TT   256     // HEAD*DIM
#define DIMG 32
#define HEADG 8
#define ACTD 8

// Scratch (no allocations allowed)
__device__ float g_H1[BB * NN * TT];
__device__ float g_EMB[BB * NN * TT];
__device__ float g_NE[BB * NN * TT];
__device__ float g_sumNH[BB * TT];
__device__ float g_sumHID[BB * TT];

// ---------------------------------------------------------------------------
// Zero the column-sum accumulators
// ---------------------------------------------------------------------------
__global__ void zero_sums_kernel() {
    int i = blockIdx.x * blockDim.x + threadIdx.x;
    if (i < BB * TT) {
        g_sumNH[i] = 0.f;
        g_sumHID[i] = 0.f;
    }
}

// ---------------------------------------------------------------------------
// Generic batched tiled GEMM: C[b] = act(A[b] @ W[b] + bias)
// Tile 64x64, TK=16, 256 threads, 4x4 micro-tile per thread.
// grid = (M/64, N/64, batch)
// ---------------------------------------------------------------------------
__global__ void gemm64_kernel(const float* __restrict__ A, long sAb, int lda,
                              const float* __restrict__ W, long sWb, int ldb,
                              const float* __restrict__ bias,
                              float* __restrict__ C, long sCb, int ldc,
                              int K, int doRelu)
{
    __shared__ float As[16][68];
    __shared__ float Bs[16][68];

    const int bz = blockIdx.z;
    const float* Ab = A + (long)bz * sAb + (long)blockIdx.x * 64 * lda;
    const float* Wb = W + (long)bz * sWb + (long)blockIdx.y * 64;
    float*       Cb = C + (long)bz * sCb + (long)blockIdx.x * 64 * ldc + (long)blockIdx.y * 64;

    const int tid = threadIdx.x;
    const int ty = tid >> 4;        // 0..15 -> rows ty*4..+3
    const int tx = tid & 15;        // 0..15 -> cols tx*4..+3

    float acc[4][4];
#pragma unroll
    for (int i = 0; i < 4; ++i)
#pragma unroll
        for (int j = 0; j < 4; ++j) acc[i][j] = 0.f;

    for (int k0 = 0; k0 < K; k0 += 16) {
#pragma unroll
        for (int i = 0; i < 4; ++i) {
            int idx = tid + i * 256;
            int r = idx >> 4, k = idx & 15;
            As[k][r] = (k0 + k < K) ? Ab[r * lda + k0 + k] : 0.f;
            int c = idx & 63, kk = idx >> 6;
            Bs[kk][c] = (k0 + kk < K) ? Wb[(long)(k0 + kk) * ldb + c] : 0.f;
        }
        __syncthreads();
#pragma unroll
        for (int k = 0; k < 16; ++k) {
            float4 a = *(const float4*)&As[k][ty * 4];
            float4 b = *(const float4*)&Bs[k][tx * 4];
            acc[0][0] = fmaf(a.x, b.x, acc[0][0]); acc[0][1] = fmaf(a.x, b.y, acc[0][1]);
            acc[0][2] = fmaf(a.x, b.z, acc[0][2]); acc[0][3] = fmaf(a.x, b.w, acc[0][3]);
            acc[1][0] = fmaf(a.y, b.x, acc[1][0]); acc[1][1] = fmaf(a.y, b.y, acc[1][1]);
            acc[1][2] = fmaf(a.y, b.z, acc[1][2]); acc[1][3] = fmaf(a.y, b.w, acc[1][3]);
            acc[2][0] = fmaf(a.z, b.x, acc[2][0]); acc[2][1] = fmaf(a.z, b.y, acc[2][1]);
            acc[2][2] = fmaf(a.z, b.z, acc[2][2]); acc[2][3] = fmaf(a.z, b.w, acc[2][3]);
            acc[3][0] = fmaf(a.w, b.x, acc[3][0]); acc[3][1] = fmaf(a.w, b.y, acc[3][1]);
            acc[3][2] = fmaf(a.w, b.z, acc[3][2]); acc[3][3] = fmaf(a.w, b.w, acc[3][3]);
        }
        __syncthreads();
    }

#pragma unroll
    for (int i = 0; i < 4; ++i) {
        int row = ty * 4 + i;
#pragma unroll
        for (int j = 0; j < 4; ++j) {
            int col = tx * 4 + j;
            float v = acc[i][j];
            if (bias) v += bias[blockIdx.y * 64 + col];
            if (doRelu) v = fmaxf(v, 0.f);
            Cb[(long)row * ldc + col] = v;
        }
    }
}

// ---------------------------------------------------------------------------
// colsum GEMM: sum over rows of relu(NE[b] @ W + bias), W = Wn (cb<4) or Wh.
// grid = (4 row-blocks, 8 col-blocks, 4 batch). Atomic accumulation.
// ---------------------------------------------------------------------------
__global__ void colsum_gemm_kernel(const float* __restrict__ NE,
                                   const float* __restrict__ Wn, const float* __restrict__ bn,
                                   const float* __restrict__ Wh, const float* __restrict__ bh,
                                   float* __restrict__ sumNH, float* __restrict__ sumHID)
{
    __shared__ float As[16][68];
    __shared__ float Bs[16][68];
    __shared__ float red[16][68];

    const int bz = blockIdx.z;
    const int cb = blockIdx.y;
    const float* W   = (cb < 4) ? Wn : Wh;
    const float* bi  = (cb < 4) ? bn : bh;
    float*       dst = (cb < 4) ? sumNH : sumHID;
    const int col0 = (cb & 3) * 64;

    const float* Ab = NE + (long)bz * (NN * TT) + (long)blockIdx.x * 64 * TT;
    const float* Wb = W + col0;

    const int tid = threadIdx.x;
    const int ty = tid >> 4;
    const int tx = tid & 15;

    float acc[4][4];
#pragma unroll
    for (int i = 0; i < 4; ++i)
#pragma unroll
        for (int j = 0; j < 4; ++j) acc[i][j] = 0.f;

    for (int k0 = 0; k0 < TT; k0 += 16) {
#pragma unroll
        for (int i = 0; i < 4; ++i) {
            int idx = tid + i * 256;
            int r = idx >> 4, k = idx & 15;
            As[k][r] = Ab[r * TT + k0 + k];
            int c = idx & 63, kk = idx >> 6;
            Bs[kk][c] = Wb[(long)(k0 + kk) * TT + c];
        }
        __syncthreads();
#pragma unroll
        for (int k = 0; k < 16; ++k) {
            float4 a = *(const float4*)&As[k][ty * 4];
            float4 b = *(const float4*)&Bs[k][tx * 4];
            acc[0][0] = fmaf(a.x, b.x, acc[0][0]); acc[0][1] = fmaf(a.x, b.y, acc[0][1]);
            acc[0][2] = fmaf(a.x, b.z, acc[0][2]); acc[0][3] = fmaf(a.x, b.w, acc[0][3]);
            acc[1][0] = fmaf(a.y, b.x, acc[1][0]); acc[1][1] = fmaf(a.y, b.y, acc[1][1]);
            acc[1][2] = fmaf(a.y, b.z, acc[1][2]); acc[1][3] = fmaf(a.y, b.w, acc[1][3]);
            acc[2][0] = fmaf(a.z, b.x, acc[2][0]); acc[2][1] = fmaf(a.z, b.y, acc[2][1]);
            acc[2][2] = fmaf(a.z, b.z, acc[2][2]); acc[2][3] = fmaf(a.z, b.w, acc[2][3]);
            acc[3][0] = fmaf(a.w, b.x, acc[3][0]); acc[3][1] = fmaf(a.w, b.y, acc[3][1]);
            acc[3][2] = fmaf(a.w, b.z, acc[3][2]); acc[3][3] = fmaf(a.w, b.w, acc[3][3]);
        }
        __syncthreads();
    }

    // bias + relu + partial column sum over this thread's 4 rows
#pragma unroll
    for (int j = 0; j < 4; ++j) {
        int col = tx * 4 + j;
        float bv = bi[col0 + col];
        float s = 0.f;
#pragma unroll
        for (int i = 0; i < 4; ++i) s += fmaxf(acc[i][j] + bv, 0.f);
        red[ty][col] = s;
    }
    __syncthreads();
    if (tid < 64) {
        float s = 0.f;
#pragma unroll
        for (int t2 = 0; t2 < 16; ++t2) s += red[t2][tid];
        atomicAdd(&dst[bz * TT + col0 + tid], s);
    }
}

// ---------------------------------------------------------------------------
// Final per-batch epilogue: l = relu(emb[b,tgt]@Wl+bl); attn softmax over DIM
// per head; out[d] = mean_h attn*sumHID; act = out@Wa + ba.
// grid = (B), 256 threads.
// ---------------------------------------------------------------------------
__global__ void final_kernel(const float* __restrict__ x,
                             const float* __restrict__ Wl, const float* __restrict__ bl,
                             const float* __restrict__ Wa, const float* __restrict__ ba,
                             float* __restrict__ out)
{
    __shared__ float er[256];
    __shared__ float av[256];
    __shared__ float prod[256];
    __shared__ float mx[8], sm[8];
    __shared__ float od[32];

    const int b = blockIdx.x;
    const int t = threadIdx.x;

    const int tgt = (int)x[(long)b * ((NN + 1) * OBSD) + NN * OBSD];  // x[b, N, 0]
    er[t] = g_EMB[((long)b * NN + tgt) * TT + t];
    __syncthreads();

    float acc = bl[t];
    for (int k = 0; k < TT; ++k) acc = fmaf(er[k], Wl[k * TT + t], acc);
    float l = fmaxf(acc, 0.f);
    av[t] = l * g_sumNH[b * TT + t];
    __syncthreads();

    if (t < HEADG) {
        float m = -1e30f;
        for (int d = 0; d < DIMG; ++d) m = fmaxf(m, av[d * HEADG + t]);
        float s = 0.f;
        for (int d = 0; d < DIMG; ++d) s += __expf(av[d * HEADG + t] - m);
        mx[t] = m; sm[t] = s;
    }
    __syncthreads();

    int h = t & (HEADG - 1);
    float attn = __expf(av[t] - mx[h]) / sm[h];
    prod[t] = attn * g_sumHID[b * TT + t];
    __syncthreads();

    if (t < DIMG) {
        float s = 0.f;
#pragma unroll
        for (int hh = 0; hh < HEADG; ++hh) s += prod[t * HEADG + hh];
        od[t] = s * (1.0f / HEADG);
    }
    __syncthreads();

    if (t < ACTD) {
        float a = ba[t];
        for (int d = 0; d < DIMG; ++d) a = fmaf(od[d], Wa[d * ACTD + t], a);
        out[b * ACTD + t] = a;
    }
}

// ---------------------------------------------------------------------------
extern "C" void kernel_launch(void* const* d_in, const int* in_sizes, int n_in,
                              void* d_out, int out_size)
{
    const float* x   = (const float*)d_in[0];
    const float* adj = (const float*)d_in[1];
    const float* We1 = (const float*)d_in[2];
    const float* be1 = (const float*)d_in[3];
    const float* We2 = (const float*)d_in[4];
    const float* be2 = (const float*)d_in[5];
    const float* Wl  = (const float*)d_in[6];
    const float* bl  = (const float*)d_in[7];
    const float* Wn  = (const float*)d_in[8];
    const float* bn  = (const float*)d_in[9];
    const float* Wh  = (const float*)d_in[10];
    const float* bh  = (const float*)d_in[11];
    const float* Wa  = (const float*)d_in[12];
    const float* ba  = (const float*)d_in[13];
    float* out = (float*)d_out;

    float *pH1, *pEMB, *pNE, *pSN, *pSH;
    cudaGetSymbolAddress((void**)&pH1, g_H1);
    cudaGetSymbolAddress((void**)&pEMB, g_EMB);
    cudaGetSymbolAddress((void**)&pNE, g_NE);
    cudaGetSymbolAddress((void**)&pSN, g_sumNH);
    cudaGetSymbolAddress((void**)&pSH, g_sumHID);

    const long xBatchStride = (long)(NN + 1) * OBSD;   // 10280
    const long matStride = (long)NN * TT;              // 65536

    zero_sums_kernel<<<(BB * TT + 255) / 256, 256>>>();

    // H1 = relu(obs @ We1 + be1)
    gemm64_kernel<<<dim3(NN / 64, TT / 64, BB), 256>>>(
        x, xBatchStride, OBSD, We1, 0, TT, be1, pH1, matStride, TT, OBSD, 1);

    // EMB = relu(H1 @ We2 + be2)
    gemm64_kernel<<<dim3(NN / 64, TT / 64, BB), 256>>>(
        pH1, matStride, TT, We2, 0, TT, be2, pEMB, matStride, TT, TT, 1);

    // NE[b] = adj @ EMB[b]
    gemm64_kernel<<<dim3(NN / 64, TT / 64, BB), 256>>>(
        adj, 0, NN, pEMB, matStride, TT, nullptr, pNE, matStride, TT, NN, 0);

    // sumNH / sumHID = colsum(relu(NE @ {Wn,Wh} + {bn,bh}))
    colsum_gemm_kernel<<<dim3(NN / 64, 8, BB), 256>>>(
        pNE, Wn, bn, Wh, bh, pSN, pSH);

    // final epilogue
    final_kernel<<<BB, 256>>>(x, Wl, bl, Wa, ba, out);
}

// round 2
// speedup vs baseline: 1.2865x; 1.2865x over previous
#include <cuda_runtime.h>

#define BB   4
#define NN   256
#define OBSD 40
#define TT   256
#define DIMG 32
#define HEADG 8
#define ACTD 8

// Scratch
__device__ float g_H1[BB * NN * TT];
__device__ float g_EMBp[2][BB * NN * TT];   // split-K partials of H1@We2 (no bias/relu)
__device__ float g_NEp[2][BB * NN * TT];    // split-K partials of adj@EMB
__device__ float g_sumNH[BB * TT];
__device__ float g_sumHID[BB * TT];

// ---------------------------------------------------------------------------
// H1 = relu(obs @ We1 + be1), M=1024 (b,n flattened), K=40. Also zeroes sums.
// grid (16,4), 256 thr, 64x64 tile, 4x4 per thread.
// ---------------------------------------------------------------------------
__global__ void h1_kernel(const float* __restrict__ x,
                          const float* __restrict__ We1,
                          const float* __restrict__ be1)
{
    if (blockIdx.x == 0 && blockIdx.y == 0) {
        for (int i = threadIdx.x; i < BB * TT; i += 256) {
            g_sumNH[i] = 0.f;
            g_sumHID[i] = 0.f;
        }
    }
    __shared__ float As[16][68];
    __shared__ float Bs[16][68];
    const int r0 = blockIdx.x * 64;
    const int c0 = blockIdx.y * 64;
    const int tid = threadIdx.x, ty = tid >> 4, tx = tid & 15;

    float acc[4][4] = {};
    for (int k0 = 0; k0 < 48; k0 += 16) {
#pragma unroll
        for (int i = 0; i < 4; ++i) {
            int idx = tid + i * 256;
            int r = idx >> 4, k = idx & 15;
            int row = r0 + r, b = row >> 8, n = row & 255;
            As[k][r] = (k0 + k < OBSD) ? x[b * ((NN + 1) * OBSD) + n * OBSD + k0 + k] : 0.f;
            int c = idx & 63, kk = idx >> 6;
            Bs[kk][c] = (k0 + kk < OBSD) ? We1[(k0 + kk) * TT + c0 + c] : 0.f;
        }
        __syncthreads();
#pragma unroll
        for (int k = 0; k < 16; ++k) {
            float a[4], b[4];
            *(float4*)a = *(const float4*)&As[k][ty * 4];
            *(float4*)b = *(const float4*)&Bs[k][tx * 4];
#pragma unroll
            for (int i = 0; i < 4; ++i)
#pragma unroll
                for (int j = 0; j < 4; ++j) acc[i][j] = fmaf(a[i], b[j], acc[i][j]);
        }
        __syncthreads();
    }
#pragma unroll
    for (int i = 0; i < 4; ++i) {
        int row = r0 + ty * 4 + i;
#pragma unroll
        for (int j = 0; j < 4; ++j) {
            int c = c0 + tx * 4 + j;
            g_H1[row * TT + c] = fmaxf(acc[i][j] + be1[c], 0.f);
        }
    }
}

// ---------------------------------------------------------------------------
// EMBp[s] = H1 @ We2 over K-half s. M=1024. grid (16,4,2)=128 blocks.
// Double-buffered smem, 1 sync/tile.
// ---------------------------------------------------------------------------
__global__ void emb_kernel(const float* __restrict__ We2)
{
    __shared__ float As[2][16][68];
    __shared__ float Bs[2][16][68];
    const int r0 = blockIdx.x * 64;
    const int c0 = blockIdx.y * 64;
    const int kb = blockIdx.z * 128;
    const int tid = threadIdx.x, ty = tid >> 4, tx = tid & 15;

    float acc[4][4] = {};
#pragma unroll
    for (int i = 0; i < 4; ++i) {
        int idx = tid + i * 256;
        int r = idx >> 4, k = idx & 15;
        As[0][k][r] = g_H1[(r0 + r) * TT + kb + k];
        int c = idx & 63, kk = idx >> 6;
        Bs[0][kk][c] = We2[(kb + kk) * TT + c0 + c];
    }
    __syncthreads();

    for (int t = 0; t < 8; ++t) {
        float ra[4], rb[4];
        if (t < 7) {
            int k0 = kb + (t + 1) * 16;
#pragma unroll
            for (int i = 0; i < 4; ++i) {
                int idx = tid + i * 256;
                int r = idx >> 4, k = idx & 15;
                ra[i] = g_H1[(r0 + r) * TT + k0 + k];
                int c = idx & 63, kk = idx >> 6;
                rb[i] = We2[(k0 + kk) * TT + c0 + c];
            }
        }
        int buf = t & 1;
#pragma unroll
        for (int k = 0; k < 16; ++k) {
            float a[4], b[4];
            *(float4*)a = *(const float4*)&As[buf][k][ty * 4];
            *(float4*)b = *(const float4*)&Bs[buf][k][tx * 4];
#pragma unroll
            for (int i = 0; i < 4; ++i)
#pragma unroll
                for (int j = 0; j < 4; ++j) acc[i][j] = fmaf(a[i], b[j], acc[i][j]);
        }
        if (t < 7) {
            int nb = buf ^ 1;
#pragma unroll
            for (int i = 0; i < 4; ++i) {
                int idx = tid + i * 256;
                int r = idx >> 4, k = idx & 15;
                As[nb][k][r] = ra[i];
                int c = idx & 63, kk = idx >> 6;
                Bs[nb][kk][c] = rb[i];
            }
            __syncthreads();
        }
    }
    float* out = &g_EMBp[blockIdx.z][0];
#pragma unroll
    for (int i = 0; i < 4; ++i)
#pragma unroll
        for (int j = 0; j < 4; ++j)
            out[(r0 + ty * 4 + i) * TT + c0 + tx * 4 + j] = acc[i][j];
}

// ---------------------------------------------------------------------------
// NEp[s][b] = adj @ EMB[b] over K-half s, EMB reconstructed on the fly from
// partials: relu(p0+p1+be2). grid (4,4,8)=128 blocks (z = b*2+s).
// ---------------------------------------------------------------------------
__global__ void ne_kernel(const float* __restrict__ adj,
                          const float* __restrict__ be2)
{
    __shared__ float As[2][16][68];
    __shared__ float Bs[2][16][68];
    const int b = blockIdx.z >> 1;
    const int s = blockIdx.z & 1;
    const int kb = s * 128;
    const int r0 = blockIdx.x * 64;
    const int c0 = blockIdx.y * 64;
    const int tid = threadIdx.x, ty = tid >> 4, tx = tid & 15;
    const int ebase = b * NN * TT;

    float acc[4][4] = {};
#pragma unroll
    for (int i = 0; i < 4; ++i) {
        int idx = tid + i * 256;
        int r = idx >> 4, k = idx & 15;
        As[0][k][r] = adj[(r0 + r) * NN + kb + k];
        int c = idx & 63, kk = idx >> 6;
        int ei = ebase + (kb + kk) * TT + c0 + c;
        Bs[0][kk][c] = fmaxf(g_EMBp[0][ei] + g_EMBp[1][ei] + be2[c0 + c], 0.f);
    }
    __syncthreads();

    for (int t = 0; t < 8; ++t) {
        float ra[4], rb[4];
        if (t < 7) {
            int k0 = kb + (t + 1) * 16;
#pragma unroll
            for (int i = 0; i < 4; ++i) {
                int idx = tid + i * 256;
                int r = idx >> 4, k = idx & 15;
                ra[i] = adj[(r0 + r) * NN + k0 + k];
                int c = idx & 63, kk = idx >> 6;
                int ei = ebase + (k0 + kk) * TT + c0 + c;
                rb[i] = fmaxf(g_EMBp[0][ei] + g_EMBp[1][ei] + be2[c0 + c], 0.f);
            }
        }
        int buf = t & 1;
#pragma unroll
        for (int k = 0; k < 16; ++k) {
            float a[4], bv[4];
            *(float4*)a = *(const float4*)&As[buf][k][ty * 4];
            *(float4*)bv = *(const float4*)&Bs[buf][k][tx * 4];
#pragma unroll
            for (int i = 0; i < 4; ++i)
#pragma unroll
                for (int j = 0; j < 4; ++j) acc[i][j] = fmaf(a[i], bv[j], acc[i][j]);
        }
        if (t < 7) {
            int nb = buf ^ 1;
#pragma unroll
            for (int i = 0; i < 4; ++i) {
                int idx = tid + i * 256;
                int r = idx >> 4, k = idx & 15;
                As[nb][k][r] = ra[i];
                int c = idx & 63, kk = idx >> 6;
                Bs[nb][kk][c] = rb[i];
            }
            __syncthreads();
        }
    }
    float* out = &g_NEp[s][b * NN * TT];
#pragma unroll
    for (int i = 0; i < 4; ++i)
#pragma unroll
        for (int j = 0; j < 4; ++j)
            out[(r0 + ty * 4 + i) * TT + c0 + tx * 4 + j] = acc[i][j];
}

// ---------------------------------------------------------------------------
// colsum of relu(NE @ {Wn|Wh} + bias); NE reconstructed (p0+p1) on A-load.
// grid (4,8,4)=128 blocks. Atomic accumulation into sums.
// ---------------------------------------------------------------------------
__global__ void colsum_kernel(const float* __restrict__ Wn, const float* __restrict__ bn,
                              const float* __restrict__ Wh, const float* __restrict__ bh)
{
    __shared__ float As[2][16][68];
    __shared__ float Bs[2][16][68];
    __shared__ float red[16][64];

    const int bz = blockIdx.z;
    const int cb = blockIdx.y;
    const float* W  = (cb < 4) ? Wn : Wh;
    const float* bi = (cb < 4) ? bn : bh;
    float* dst = (cb < 4) ? g_sumNH : g_sumHID;
    const int c0 = (cb & 3) * 64;
    const int r0 = blockIdx.x * 64;
    const int abase = bz * NN * TT;
    const int tid = threadIdx.x, ty = tid >> 4, tx = tid & 15;

    float acc[4][4] = {};
#pragma unroll
    for (int i = 0; i < 4; ++i) {
        int idx = tid + i * 256;
        int r = idx >> 4, k = idx & 15;
        int ai = abase + (r0 + r) * TT + k;
        As[0][k][r] = g_NEp[0][ai] + g_NEp[1][ai];
        int c = idx & 63, kk = idx >> 6;
        Bs[0][kk][c] = W[kk * TT + c0 + c];
    }
    __syncthreads();

    for (int t = 0; t < 16; ++t) {
        float ra[4], rb[4];
        if (t < 15) {
            int k0 = (t + 1) * 16;
#pragma unroll
            for (int i = 0; i < 4; ++i) {
                int idx = tid + i * 256;
                int r = idx >> 4, k = idx & 15;
                int ai = abase + (r0 + r) * TT + k0 + k;
                ra[i] = g_NEp[0][ai] + g_NEp[1][ai];
                int c = idx & 63, kk = idx >> 6;
                rb[i] = W[(k0 + kk) * TT + c0 + c];
            }
        }
        int buf = t & 1;
#pragma unroll
        for (int k = 0; k < 16; ++k) {
            float a[4], bv[4];
            *(float4*)a = *(const float4*)&As[buf][k][ty * 4];
            *(float4*)bv = *(const float4*)&Bs[buf][k][tx * 4];
#pragma unroll
            for (int i = 0; i < 4; ++i)
#pragma unroll
                for (int j = 0; j < 4; ++j) acc[i][j] = fmaf(a[i], bv[j], acc[i][j]);
        }
        if (t < 15) {
            int nb = buf ^ 1;
#pragma unroll
            for (int i = 0; i < 4; ++i) {
                int idx = tid + i * 256;
                int r = idx >> 4, k = idx & 15;
                As[nb][k][r] = ra[i];
                int c = idx & 63, kk = idx >> 6;
                Bs[nb][kk][c] = rb[i];
            }
            __syncthreads();
        }
    }

#pragma unroll
    for (int j = 0; j < 4; ++j) {
        int col = tx * 4 + j;
        float bv = bi[c0 + col];
        float sum = 0.f;
#pragma unroll
        for (int i = 0; i < 4; ++i) sum += fmaxf(acc[i][j] + bv, 0.f);
        red[ty][col] = sum;
    }
    __syncthreads();
    if (tid < 64) {
        float s = 0.f;
#pragma unroll
        for (int t2 = 0; t2 < 16; ++t2) s += red[t2][tid];
        atomicAdd(&dst[bz * TT + c0 + tid], s);
    }
}

// ---------------------------------------------------------------------------
// Final epilogue: reconstruct emb[b,tgt], l = relu(@Wl+bl), softmax, output.
// ---------------------------------------------------------------------------
__global__ void final_kernel(const float* __restrict__ x,
                             const float* __restrict__ be2,
                             const float* __restrict__ Wl, const float* __restrict__ bl,
                             const float* __restrict__ Wa, const float* __restrict__ ba,
                             float* __restrict__ out)
{
    __shared__ float er[256];
    __shared__ float av[256];
    __shared__ float prod[256];
    __shared__ float mx[8], sm[8];
    __shared__ float od[32];

    const int b = blockIdx.x;
    const int t = threadIdx.x;

    const int tgt = (int)x[(long)b * ((NN + 1) * OBSD) + NN * OBSD];
    int ei = (b * NN + tgt) * TT + t;
    er[t] = fmaxf(g_EMBp[0][ei] + g_EMBp[1][ei] + be2[t], 0.f);
    __syncthreads();

    float acc = bl[t];
#pragma unroll 8
    for (int k = 0; k < TT; ++k) acc = fmaf(er[k], Wl[k * TT + t], acc);
    float l = fmaxf(acc, 0.f);
    av[t] = l * g_sumNH[b * TT + t];
    __syncthreads();

    if (t < HEADG) {
        float m = -1e30f;
        for (int d = 0; d < DIMG; ++d) m = fmaxf(m, av[d * HEADG + t]);
        float s = 0.f;
        for (int d = 0; d < DIMG; ++d) s += __expf(av[d * HEADG + t] - m);
        mx[t] = m; sm[t] = s;
    }
    __syncthreads();

    int h = t & (HEADG - 1);
    float attn = __expf(av[t] - mx[h]) / sm[h];
    prod[t] = attn * g_sumHID[b * TT + t];
    __syncthreads();

    if (t < DIMG) {
        float s = 0.f;
#pragma unroll
        for (int hh = 0; hh < HEADG; ++hh) s += prod[t * HEADG + hh];
        od[t] = s * (1.0f / HEADG);
    }
    __syncthreads();

    if (t < ACTD) {
        float a = ba[t];
#pragma unroll
        for (int d = 0; d < DIMG; ++d) a = fmaf(od[d], Wa[d * ACTD + t], a);
        out[b * ACTD + t] = a;
    }
}

// ---------------------------------------------------------------------------
extern "C" void kernel_launch(void* const* d_in, const int* in_sizes, int n_in,
                              void* d_out, int out_size)
{
    const float* x   = (const float*)d_in[0];
    const float* adj = (const float*)d_in[1];
    const float* We1 = (const float*)d_in[2];
    const float* be1 = (const float*)d_in[3];
    const float* We2 = (const float*)d_in[4];
    const float* be2 = (const float*)d_in[5];
    const float* Wl  = (const float*)d_in[6];
    const float* bl  = (const float*)d_in[7];
    const float* Wn  = (const float*)d_in[8];
    const float* bn  = (const float*)d_in[9];
    const float* Wh  = (const float*)d_in[10];
    const float* bh  = (const float*)d_in[11];
    const float* Wa  = (const float*)d_in[12];
    const float* ba  = (const float*)d_in[13];
    float* out = (float*)d_out;

    h1_kernel<<<dim3(16, 4), 256>>>(x, We1, be1);
    emb_kernel<<<dim3(16, 4, 2), 256>>>(We2);
    ne_kernel<<<dim3(4, 4, 8), 256>>>(adj, be2);
    colsum_kernel<<<dim3(4, 8, 4), 256>>>(Wn, bn, Wh, bh);
    final_kernel<<<BB, 256>>>(x, be2, Wl, bl, Wa, ba, out);
}